// round 14
// baseline (speedup 1.0000x reference)
#include <cuda_runtime.h>
#include <math.h>

#define NN 768
#define CC 384
#define HH 12
#define PLANE (NN * NN)
#define SC 0.57735026919f

__device__ float g_wcat[CC * 1152];
__device__ float g_bcat[1152];
__device__ float g_raw[NN * 1152];   // [q][qpt144|kpt144|vpt288|qs192|ks192|vs192]
__device__ float g_qg[NN * 144];
__device__ float g_kg[NN * 144];
__device__ float g_vg[NN * 288];
__device__ float g_qn[NN * HH];
__device__ float g_kn[NN * HH];
__device__ float g_u[NN * 336];
__device__ float g_v[NN * 336];
__device__ float g_qadd[NN * HH];
__device__ float g_kadd[NN * HH];
__device__ float g_attn[(size_t)HH * PLANE];
__device__ float g_rpg[NN * 288];
__device__ float g_final[NN * 2112];
__device__ float g_tmp[NN * CC];
__device__ float g_act1[NN * CC];
__device__ float g_x1[NN * CC];
__device__ float g_x2[NN * CC];

__global__ void pack_kernel(const float* __restrict__ wq, const float* __restrict__ wk,
                            const float* __restrict__ wv, const float* __restrict__ wqs,
                            const float* __restrict__ wks, const float* __restrict__ wvs,
                            const float* __restrict__ bq, const float* __restrict__ bk,
                            const float* __restrict__ bv)
{
    int idx = blockIdx.x * blockDim.x + threadIdx.x;
    if (idx < CC * 1152) {
        int c = idx / 1152, o = idx - c * 1152;
        float v;
        if (o < 144)      v = wq[c * 144 + o];
        else if (o < 288) v = wk[c * 144 + (o - 144)];
        else if (o < 576) v = wv[c * 288 + (o - 288)];
        else if (o < 768) v = wqs[c * 192 + (o - 576)];
        else if (o < 960) v = wks[c * 192 + (o - 768)];
        else              v = wvs[c * 192 + (o - 960)];
        g_wcat[idx] = v;
    }
    if (idx < 1152) {
        float b = 0.f;
        if (idx < 144)      b = bq[idx];
        else if (idx < 288) b = bk[idx - 144];
        else if (idx < 576) b = bv[idx - 288];
        g_bcat[idx] = b;
    }
}

// C[M,N]=A[M,K]@W[K,N]+bias. BM=32, BN=64, BK=16, 128 threads, 4x4 microtile.
// M%32==0, N%64==0, K%16==0. grid = (N/64, M/32)
__global__ void __launch_bounds__(128) gemm_kernel(
    const float* __restrict__ A, const float* __restrict__ W,
    const float* __restrict__ bias, float* __restrict__ C,
    int M, int N, int K, int relu)
{
    __shared__ float sA[16][36];   // [kk][m] transposed, padded
    __shared__ float sB[16][64];   // [kk][n]
    int tid = threadIdx.x;
    int m0 = blockIdx.y << 5, n0 = blockIdx.x << 6;
    int tm = (tid >> 4) << 2, tn = (tid & 15) << 2;
    float acc[4][4] = {};
    for (int k0 = 0; k0 < K; k0 += 16) {
        {
            int m = tid >> 2, kq = (tid & 3) << 2;
            float4 a = *(const float4*)(A + (size_t)(m0 + m) * K + k0 + kq);
            sA[kq + 0][m] = a.x; sA[kq + 1][m] = a.y; sA[kq + 2][m] = a.z; sA[kq + 3][m] = a.w;
        }
        {
            int r = tid >> 4, n = (tid & 15) << 2;
            *(float4*)&sB[r][n]     = *(const float4*)(W + (size_t)(k0 + r) * N + n0 + n);
            *(float4*)&sB[r + 8][n] = *(const float4*)(W + (size_t)(k0 + r + 8) * N + n0 + n);
        }
        __syncthreads();
        #pragma unroll
        for (int kk = 0; kk < 16; kk++) {
            float4 a = *(const float4*)&sA[kk][tm];
            float4 b = *(const float4*)&sB[kk][tn];
            acc[0][0] += a.x * b.x; acc[0][1] += a.x * b.y; acc[0][2] += a.x * b.z; acc[0][3] += a.x * b.w;
            acc[1][0] += a.y * b.x; acc[1][1] += a.y * b.y; acc[1][2] += a.y * b.z; acc[1][3] += a.y * b.w;
            acc[2][0] += a.z * b.x; acc[2][1] += a.z * b.y; acc[2][2] += a.z * b.z; acc[2][3] += a.z * b.w;
            acc[3][0] += a.w * b.x; acc[3][1] += a.w * b.y; acc[3][2] += a.w * b.z; acc[3][3] += a.w * b.w;
        }
        __syncthreads();
    }
    #pragma unroll
    for (int i = 0; i < 4; i++) {
        int row = m0 + tm + i, col = n0 + tn;
        float4 v = make_float4(acc[i][0] + bias[col], acc[i][1] + bias[col + 1],
                               acc[i][2] + bias[col + 2], acc[i][3] + bias[col + 3]);
        if (relu) { v.x = fmaxf(v.x, 0.f); v.y = fmaxf(v.y, 0.f); v.z = fmaxf(v.z, 0.f); v.w = fmaxf(v.w, 0.f); }
        *(float4*)(C + (size_t)row * N + col) = v;
    }
}

__global__ void __launch_bounds__(384) rigid_kernel(const float* __restrict__ rot,
                                                    const float* __restrict__ trans)
{
    __shared__ float sq[144], sk[144];
    int q = blockIdx.x, t = threadIdx.x;
    const float* R = rot + q * 9;
    const float* T = trans + q * 3;
    const float* raw = g_raw + (size_t)q * 1152;
    for (int wi = t; wi < 576; wi += 384) {
        int base, P, lw;
        float* dst;
        if (wi < 144)      { base = 0;   P = 4; lw = wi;       dst = g_qg + q * 144; }
        else if (wi < 288) { base = 144; P = 4; lw = wi - 144; dst = g_kg + q * 144; }
        else               { base = 288; P = 8; lw = wi - 288; dst = g_vg + q * 288; }
        int per = 3 * P;
        int h = lw / per, r = lw - h * per, p = r / 3, i = r - p * 3;
        float l0 = raw[base + h * per + 0 * P + p];
        float l1 = raw[base + h * per + 1 * P + p];
        float l2 = raw[base + h * per + 2 * P + p];
        float v = R[i * 3 + 0] * l0 + R[i * 3 + 1] * l1 + R[i * 3 + 2] * l2 + T[i];
        dst[h * per + p * 3 + i] = v;
        if (wi < 144) sq[lw] = v;
        else if (wi < 288) sk[lw] = v;
    }
    __syncthreads();
    if (t < 24) {
        int h = t % 12;
        const float* sp = (t < 12) ? sq : sk;
        float a = 0.f;
        #pragma unroll
        for (int j = 0; j < 12; j++) { float x = sp[h * 12 + j]; a += x * x; }
        if (t < 12) g_qn[q * 12 + h] = a; else g_kn[q * 12 + h] = a;
    }
    for (int j = t; j < 192; j += 384) g_raw[(size_t)q * 1152 + 576 + j] *= 0.25f;
}

__global__ void __launch_bounds__(128) prep_kernel(const float* __restrict__ tpw)
{
    __shared__ float pw[12];
    int q = blockIdx.x, t = threadIdx.x;
    if (t < 12) pw[t] = 0.23570226039551584f * log1pf(__expf(tpw[t]));
    __syncthreads();
    for (int i = t; i < 336; i += 128) {
        int h = i / 28, j = i - h * 28;
        float u, v;
        if (j < 12) {
            u = g_qg[q * 144 + h * 12 + j] * pw[h] * SC;
            v = g_kg[q * 144 + h * 12 + j];
        } else {
            u = g_raw[(size_t)q * 1152 + 576 + h * 16 + (j - 12)] * SC;
            v = g_raw[(size_t)q * 1152 + 768 + h * 16 + (j - 12)];
        }
        g_u[q * 336 + i] = u;
        g_v[q * 336 + i] = v;
    }
    if (t < 12) {
        g_qadd[q * 12 + t] = -0.5f * SC * pw[t] * g_qn[q * 12 + t];
        g_kadd[q * 12 + t] = -0.5f * SC * pw[t] * g_kn[q * 12 + t];
    }
}

// fused logits: 2 (q,k) pairs x 12 heads per thread
__global__ void __launch_bounds__(256) bias_kernel(
    const float* __restrict__ in2d, const float* __restrict__ w2d,
    const float* __restrict__ b2d, const float* __restrict__ mask)
{
    __shared__ float sw[12][128];
    __shared__ float sb[12];
    int tid = threadIdx.x;
    for (int i = tid; i < 1536; i += 256) {
        int h = i >> 7, c = i & 127;
        sw[h][c] = w2d[c * 12 + h];
    }
    if (tid < 12) sb[tid] = b2d[tid];
    __syncthreads();
    int kx = tid & 15, qy = tid >> 4;
    int q = (blockIdx.y << 4) + qy;
    int kb = (blockIdx.x << 5) + kx;
    const float* p0 = in2d + ((size_t)q * NN + kb) * 128;
    float acc[2][12] = {};
    for (int c = 0; c < 128; c += 8) {
        float4 v00 = *(const float4*)(p0 + c);
        float4 v01 = *(const float4*)(p0 + c + 4);
        float4 v10 = *(const float4*)(p0 + 16 * 128 + c);
        float4 v11 = *(const float4*)(p0 + 16 * 128 + c + 4);
        #pragma unroll
        for (int h = 0; h < 12; h++) {
            float4 w0 = *(const float4*)&sw[h][c];
            float4 w1 = *(const float4*)&sw[h][c + 4];
            acc[0][h] += v00.x * w0.x + v00.y * w0.y + v00.z * w0.z + v00.w * w0.w
                       + v01.x * w1.x + v01.y * w1.y + v01.z * w1.z + v01.w * w1.w;
            acc[1][h] += v10.x * w0.x + v10.y * w0.y + v10.z * w0.z + v10.w * w0.w
                       + v11.x * w1.x + v11.y * w1.y + v11.z * w1.z + v11.w * w1.w;
        }
    }
    float mq = mask[q];
    float mt0 = SC * 1e5f * (1.f - mq * mask[kb]);
    float mt1 = SC * 1e5f * (1.f - mq * mask[kb + 16]);
    const float* up = g_u + q * 336;
    const float* vp0 = g_v + kb * 336;
    const float* vp1 = g_v + (kb + 16) * 336;
    const float* qa = g_qadd + q * 12;
    const float* ka0 = g_kadd + kb * 12;
    const float* ka1 = g_kadd + (kb + 16) * 12;
    #pragma unroll 2
    for (int h = 0; h < 12; h++) {
        float d0 = 0.f, d1 = 0.f;
        #pragma unroll
        for (int jj = 0; jj < 7; jj++) {
            float4 uu = *(const float4*)(up + h * 28 + jj * 4);
            float4 a = *(const float4*)(vp0 + h * 28 + jj * 4);
            float4 b = *(const float4*)(vp1 + h * 28 + jj * 4);
            d0 += uu.x * a.x + uu.y * a.y + uu.z * a.z + uu.w * a.w;
            d1 += uu.x * b.x + uu.y * b.y + uu.z * b.z + uu.w * b.w;
        }
        float base = (acc[0][h] + sb[h]) * SC + qa[h];
        float base1 = (acc[1][h] + sb[h]) * SC + qa[h];
        g_attn[(size_t)h * PLANE + (size_t)q * NN + kb]      = d0 + base  + ka0[h] - mt0;
        g_attn[(size_t)h * PLANE + (size_t)q * NN + kb + 16] = d1 + base1 + ka1[h] - mt1;
    }
}

// warp-shuffle softmax over k (768 per row), 256 threads, 3 short barriers
__global__ void __launch_bounds__(256) softmax_kernel()
{
    __shared__ float sred[8];
    __shared__ float sbc;
    int b = blockIdx.x;
    int h = b / NN, q = b - h * NN;
    float* row = g_attn + (size_t)h * PLANE + (size_t)q * NN;
    int t = threadIdx.x;
    int lane = t & 31, warp = t >> 5;
    float v0 = row[t], v1 = row[t + 256], v2 = row[t + 512];
    float m = fmaxf(v0, fmaxf(v1, v2));
    #pragma unroll
    for (int o = 16; o > 0; o >>= 1) m = fmaxf(m, __shfl_xor_sync(0xffffffff, m, o));
    if (lane == 0) sred[warp] = m;
    __syncthreads();
    if (t == 0) {
        float mm = sred[0];
        #pragma unroll
        for (int i = 1; i < 8; i++) mm = fmaxf(mm, sred[i]);
        sbc = mm;
    }
    __syncthreads();
    m = sbc;
    float e0 = __expf(v0 - m), e1 = __expf(v1 - m), e2 = __expf(v2 - m);
    float s = e0 + e1 + e2;
    #pragma unroll
    for (int o = 16; o > 0; o >>= 1) s += __shfl_xor_sync(0xffffffff, s, o);
    if (lane == 0) sred[warp] = s;
    __syncthreads();
    if (t == 0) {
        float ss = sred[0];
        #pragma unroll
        for (int i = 1; i < 8; i++) ss += sred[i];
        sbc = 1.f / ss;
    }
    __syncthreads();
    float inv = sbc;
    row[t] = e0 * inv; row[t + 256] = e1 * inv; row[t + 512] = e2 * inv;
}

// per-head attn @ [vs|vg]
__global__ void __launch_bounds__(256) headgemm_kernel()
{
    __shared__ float s_attn[64 * 65];
    __shared__ float s_v[64 * 40];
    int tid = threadIdx.x;
    int q0 = blockIdx.x << 6, h = blockIdx.y;
    const float* ap = g_attn + (size_t)h * PLANE;
    int ql = tid & 63, cg = tid >> 6;
    float acc[10] = {};
    for (int kt = 0; kt < NN; kt += 64) {
        #pragma unroll
        for (int i = 0; i < 16; i++) {
            int id = tid + (i << 8);
            int r = id >> 6, c = id & 63;
            s_attn[r * 65 + c] = ap[(size_t)(q0 + r) * NN + kt + c];
        }
        #pragma unroll
        for (int i = 0; i < 10; i++) {
            int id = tid + (i << 8);
            int r = id / 40, c = id - r * 40;
            float v;
            if (c < 16) v = g_raw[(size_t)(kt + r) * 1152 + 960 + h * 16 + c];
            else        v = g_vg[(kt + r) * 288 + h * 24 + (c - 16)];
            s_v[r * 40 + c] = v;
        }
        __syncthreads();
        #pragma unroll 8
        for (int kk = 0; kk < 64; kk++) {
            float a = s_attn[ql * 65 + kk];
            const float* vr = s_v + kk * 40 + cg * 10;
            #pragma unroll
            for (int c = 0; c < 10; c++) acc[c] += a * vr[c];
        }
        __syncthreads();
    }
    int q = q0 + ql;
    #pragma unroll
    for (int c = 0; c < 10; c++) {
        int col = cg * 10 + c;
        if (col < 16) g_final[(size_t)q * 2112 + h * 16 + col] = acc[c];
        else          g_rpg[q * 288 + h * 24 + (col - 16)] = acc[c];
    }
}

// res_2d: split-k halves, attn transposed [k][12h]
__global__ void __launch_bounds__(256) res2d_kernel(const float* __restrict__ in2d)
{
    __shared__ __align__(16) float s_attn[NN * 12];
    __shared__ float s_part[12 * 128];
    int q = blockIdx.x, tid = threadIdx.x;
    #pragma unroll
    for (int h = 0; h < 12; h++)
        for (int k = tid; k < NN; k += 256)
            s_attn[k * 12 + h] = g_attn[(size_t)h * PLANE + (size_t)q * NN + k];
    __syncthreads();
    int c = tid & 127, hg = tid >> 7;
    const float* base = in2d + ((size_t)q * NN + hg * 384) * 128 + c;
    const float* ap = s_attn + hg * 384 * 12;
    float acc[12] = {};
    for (int k0 = 0; k0 < 384; k0 += 8) {
        float vbuf[8];
        #pragma unroll
        for (int j = 0; j < 8; j++)
            vbuf[j] = base[(size_t)(k0 + j) * 128];
        #pragma unroll
        for (int j = 0; j < 8; j++) {
            float v = vbuf[j];
            const float* a = ap + (k0 + j) * 12;
            float4 a0 = *(const float4*)(a);
            float4 a1 = *(const float4*)(a + 4);
            float4 a2 = *(const float4*)(a + 8);
            acc[0] += v * a0.x; acc[1]  += v * a0.y; acc[2]  += v * a0.z; acc[3]  += v * a0.w;
            acc[4] += v * a1.x; acc[5]  += v * a1.y; acc[6]  += v * a1.z; acc[7]  += v * a1.w;
            acc[8] += v * a2.x; acc[9]  += v * a2.y; acc[10] += v * a2.z; acc[11] += v * a2.w;
        }
    }
    if (hg == 1) {
        #pragma unroll
        for (int h = 0; h < 12; h++) s_part[h * 128 + c] = acc[h];
    }
    __syncthreads();
    if (hg == 0) {
        float* f = g_final + (size_t)q * 2112 + 576;
        #pragma unroll
        for (int h = 0; h < 12; h++) f[h * 128 + c] = acc[h] + s_part[h * 128 + c];
    }
}

__global__ void __launch_bounds__(96) rpl_kernel(const float* __restrict__ rot,
                                                 const float* __restrict__ trans)
{
    int q = blockIdx.x, wi = threadIdx.x;
    int h = wi >> 3, p = wi & 7;
    const float* R = rot + q * 9;
    const float* T = trans + q * 3;
    const float* g = g_rpg + q * 288 + h * 24 + p * 3;
    float g0 = g[0] - T[0], g1 = g[1] - T[1], g2 = g[2] - T[2];
    float l0 = R[0] * g0 + R[3] * g1 + R[6] * g2;
    float l1 = R[1] * g0 + R[4] * g1 + R[7] * g2;
    float l2 = R[2] * g0 + R[5] * g1 + R[8] * g2;
    float* f = g_final + (size_t)q * 2112;
    f[192 + h * 8 + p] = l0;
    f[288 + h * 8 + p] = l1;
    f[384 + h * 8 + p] = l2;
    f[480 + h * 8 + p] = sqrtf(fmaxf(l0 * l0 + l1 * l1 + l2 * l2, 1e-16f));
}

__global__ void __launch_bounds__(128) ln_kernel(
    const float* __restrict__ A, const float* __restrict__ B,
    const float* __restrict__ s, const float* __restrict__ bi,
    float* __restrict__ out, int ostride)
{
    __shared__ float r1[128], r2[128];
    int q = blockIdx.x, t = threadIdx.x;
    float x0 = A[q * 384 + t] + B[q * 384 + t];
    float x1 = A[q * 384 + t + 128] + B[q * 384 + t + 128];
    float x2 = A[q * 384 + t + 256] + B[q * 384 + t + 256];
    r1[t] = x0 + x1 + x2;
    r2[t] = x0 * x0 + x1 * x1 + x2 * x2;
    __syncthreads();
    for (int o = 64; o > 0; o >>= 1) {
        if (t < o) { r1[t] += r1[t + o]; r2[t] += r2[t + o]; }
        __syncthreads();
    }
    float mu = r1[0] * (1.f / 384.f);
    float var = r2[0] * (1.f / 384.f) - mu * mu;
    float inv = rsqrtf(var + 1e-5f);
    out[(size_t)q * ostride + t]       = (x0 - mu) * inv * s[t] + bi[t];
    out[(size_t)q * ostride + t + 128] = (x1 - mu) * inv * s[t + 128] + bi[t + 128];
    out[(size_t)q * ostride + t + 256] = (x2 - mu) * inv * s[t + 256] + bi[t + 256];
}

__global__ void __launch_bounds__(192) quat_kernel(
    float* __restrict__ out, const float* __restrict__ rot,
    const float* __restrict__ trans, const float* __restrict__ wq,
    const float* __restrict__ bq)
{
    __shared__ float sv[6];
    int q = blockIdx.x, t = threadIdx.x;
    int warp = t >> 5, lane = t & 31;
    const float* act = out + (size_t)q * 396;
    float acc = 0.f;
    for (int c = lane; c < 384; c += 32) acc += act[c] * wq[c * 6 + warp];
    #pragma unroll
    for (int o = 16; o > 0; o >>= 1) acc += __shfl_down_sync(0xffffffff, acc, o);
    if (lane == 0) sv[warp] = acc + bq[warp];
    __syncthreads();
    if (t == 0) {
        float a = sv[0], b = sv[1], c = sv[2];
        float inv = rsqrtf(1.f + a * a + b * b + c * c);
        float w = inv, x = a * inv, y = b * inv, z = c * inv;
        float ru[9] = {
            1.f - 2.f * (y * y + z * z), 2.f * (x * y - w * z), 2.f * (x * z + w * y),
            2.f * (x * y + w * z), 1.f - 2.f * (x * x + z * z), 2.f * (y * z - w * x),
            2.f * (x * z - w * y), 2.f * (y * z + w * x), 1.f - 2.f * (x * x + y * y)
        };
        const float* R = rot + q * 9;
        const float* T = trans + q * 3;
        float* o9 = out + (size_t)q * 396 + 384;
        #pragma unroll
        for (int i = 0; i < 3; i++)
            #pragma unroll
            for (int j = 0; j < 3; j++)
                o9[i * 3 + j] = R[i * 3 + 0] * ru[0 + j] + R[i * 3 + 1] * ru[3 + j] + R[i * 3 + 2] * ru[6 + j];
        float t0 = sv[3], t1 = sv[4], t2 = sv[5];
        #pragma unroll
        for (int i = 0; i < 3; i++)
            out[(size_t)q * 396 + 393 + i] = R[i * 3 + 0] * t0 + R[i * 3 + 1] * t1 + R[i * 3 + 2] * t2 + T[i];
    }
}

extern "C" void kernel_launch(void* const* d_in, const int* in_sizes, int n_in,
                              void* d_out, int out_size)
{
    const float* in1d  = (const float*)d_in[0];
    const float* in2d  = (const float*)d_in[1];
    const float* mask  = (const float*)d_in[2];
    const float* rot   = (const float*)d_in[3];
    const float* trans = (const float*)d_in[4];
    const float* wqp   = (const float*)d_in[5];
    const float* bqp   = (const float*)d_in[6];
    const float* wkp   = (const float*)d_in[7];
    const float* bkp   = (const float*)d_in[8];
    const float* wvp   = (const float*)d_in[9];
    const float* bvp   = (const float*)d_in[10];
    const float* wqs   = (const float*)d_in[11];
    const float* wks   = (const float*)d_in[12];
    const float* wvs   = (const float*)d_in[13];
    const float* tpw   = (const float*)d_in[14];
    const float* w2d   = (const float*)d_in[15];
    const float* b2d   = (const float*)d_in[16];
    const float* wout  = (const float*)d_in[17];
    const float* bout  = (const float*)d_in[18];
    const float* ln1s  = (const float*)d_in[19];
    const float* ln1b  = (const float*)d_in[20];
    const float* wt1   = (const float*)d_in[21];
    const float* bt1   = (const float*)d_in[22];
    const float* wt2   = (const float*)d_in[23];
    const float* bt2   = (const float*)d_in[24];
    const float* wt3   = (const float*)d_in[25];
    const float* bt3   = (const float*)d_in[26];
    const float* ln2s  = (const float*)d_in[27];
    const float* ln2b  = (const float*)d_in[28];
    const float* wquat = (const float*)d_in[29];
    const float* bquat = (const float*)d_in[30];
    float* out = (float*)d_out;

    float *p_wcat, *p_bcat, *p_raw, *p_final, *p_tmp, *p_act1, *p_x1, *p_x2;
    cudaGetSymbolAddress((void**)&p_wcat, g_wcat);
    cudaGetSymbolAddress((void**)&p_bcat, g_bcat);
    cudaGetSymbolAddress((void**)&p_raw, g_raw);
    cudaGetSymbolAddress((void**)&p_final, g_final);
    cudaGetSymbolAddress((void**)&p_tmp, g_tmp);
    cudaGetSymbolAddress((void**)&p_act1, g_act1);
    cudaGetSymbolAddress((void**)&p_x1, g_x1);
    cudaGetSymbolAddress((void**)&p_x2, g_x2);

    pack_kernel<<<(CC * 1152 + 255) / 256, 256>>>(wqp, wkp, wvp, wqs, wks, wvs, bqp, bkp, bvp);
    gemm_kernel<<<dim3(1152 / 64, NN / 32), 128>>>(in1d, p_wcat, p_bcat, p_raw, NN, 1152, CC, 0);
    rigid_kernel<<<NN, 384>>>(rot, trans);
    prep_kernel<<<NN, 128>>>(tpw);
    bias_kernel<<<dim3(NN / 32, NN / 16), 256>>>(in2d, w2d, b2d, mask);
    softmax_kernel<<<HH * NN, 256>>>();
    headgemm_kernel<<<dim3(NN / 64, HH), 256>>>();
    res2d_kernel<<<NN, 256>>>(in2d);
    rpl_kernel<<<NN, 96>>>(rot, trans);
    gemm_kernel<<<dim3(CC / 64, NN / 32), 128>>>(p_final, wout, bout, p_tmp, NN, CC, 2112, 0);
    ln_kernel<<<NN, 128>>>(in1d, p_tmp, ln1s, ln1b, p_act1, 384);
    gemm_kernel<<<dim3(CC / 64, NN / 32), 128>>>(p_act1, wt1, bt1, p_x1, NN, CC, CC, 1);
    gemm_kernel<<<dim3(CC / 64, NN / 32), 128>>>(p_x1, wt2, bt2, p_x2, NN, CC, CC, 1);
    gemm_kernel<<<dim3(CC / 64, NN / 32), 128>>>(p_x2, wt3, bt3, p_tmp, NN, CC, CC, 0);
    ln_kernel<<<NN, 128>>>(p_act1, p_tmp, ln2s, ln2b, out, 396);
    quat_kernel<<<NN, 192>>>(out, rot, trans, wquat, bquat);
}

// round 15
// speedup vs baseline: 1.4411x; 1.4411x over previous
#include <cuda_runtime.h>
#include <math.h>

#define NN 768
#define CC 384
#define HH 12
#define PLANE (NN * NN)
#define SC 0.57735026919f

__device__ float g_wcat[CC * 1152];
__device__ float g_bcat[1152];
__device__ float g_raw[NN * 1152];   // [q][qpt144|kpt144|vpt288|qs192|ks192|vs192]
__device__ float g_qg[NN * 144];
__device__ float g_kg[NN * 144];
__device__ float g_vg[NN * 288];
__device__ float g_qn[NN * HH];
__device__ float g_kn[NN * HH];
__device__ float g_u[NN * 336];
__device__ float g_v[NN * 336];
__device__ float g_qadd[NN * HH];
__device__ float g_kadd[NN * HH];
__device__ float g_attn[(size_t)HH * PLANE];
__device__ float g_rpg[NN * 288];
__device__ float g_final[NN * 2112];
__device__ float g_tmp[NN * CC];
__device__ float g_act1[NN * CC];
__device__ float g_x1[NN * CC];
__device__ float g_x2[NN * CC];

__global__ void pack_kernel(const float* __restrict__ wq, const float* __restrict__ wk,
                            const float* __restrict__ wv, const float* __restrict__ wqs,
                            const float* __restrict__ wks, const float* __restrict__ wvs,
                            const float* __restrict__ bq, const float* __restrict__ bk,
                            const float* __restrict__ bv)
{
    int idx = blockIdx.x * blockDim.x + threadIdx.x;
    if (idx < CC * 1152) {
        int c = idx / 1152, o = idx - c * 1152;
        float v;
        if (o < 144)      v = wq[c * 144 + o];
        else if (o < 288) v = wk[c * 144 + (o - 144)];
        else if (o < 576) v = wv[c * 288 + (o - 288)];
        else if (o < 768) v = wqs[c * 192 + (o - 576)];
        else if (o < 960) v = wks[c * 192 + (o - 768)];
        else              v = wvs[c * 192 + (o - 960)];
        g_wcat[idx] = v;
    }
    if (idx < 1152) {
        float b = 0.f;
        if (idx < 144)      b = bq[idx];
        else if (idx < 288) b = bk[idx - 144];
        else if (idx < 576) b = bv[idx - 288];
        g_bcat[idx] = b;
    }
}

// C[M,N]=A[M,K]@W[K,N]+bias. BM=32, BN=64, BK=16, 128 threads, 4x4 microtile.
// M%32==0, N%64==0, K%16==0. grid = (N/64, M/32)
__global__ void __launch_bounds__(128) gemm_kernel(
    const float* __restrict__ A, const float* __restrict__ W,
    const float* __restrict__ bias, float* __restrict__ C,
    int M, int N, int K, int relu)
{
    __shared__ float sA[16][36];   // [kk][m] transposed, padded
    __shared__ float sB[16][64];   // [kk][n]
    int tid = threadIdx.x;
    int m0 = blockIdx.y << 5, n0 = blockIdx.x << 6;
    int tm = (tid >> 4) << 2, tn = (tid & 15) << 2;
    float acc[4][4] = {};
    for (int k0 = 0; k0 < K; k0 += 16) {
        {
            int m = tid >> 2, kq = (tid & 3) << 2;
            float4 a = *(const float4*)(A + (size_t)(m0 + m) * K + k0 + kq);
            sA[kq + 0][m] = a.x; sA[kq + 1][m] = a.y; sA[kq + 2][m] = a.z; sA[kq + 3][m] = a.w;
        }
        {
            int r = tid >> 4, n = (tid & 15) << 2;
            *(float4*)&sB[r][n]     = *(const float4*)(W + (size_t)(k0 + r) * N + n0 + n);
            *(float4*)&sB[r + 8][n] = *(const float4*)(W + (size_t)(k0 + r + 8) * N + n0 + n);
        }
        __syncthreads();
        #pragma unroll
        for (int kk = 0; kk < 16; kk++) {
            float4 a = *(const float4*)&sA[kk][tm];
            float4 b = *(const float4*)&sB[kk][tn];
            acc[0][0] += a.x * b.x; acc[0][1] += a.x * b.y; acc[0][2] += a.x * b.z; acc[0][3] += a.x * b.w;
            acc[1][0] += a.y * b.x; acc[1][1] += a.y * b.y; acc[1][2] += a.y * b.z; acc[1][3] += a.y * b.w;
            acc[2][0] += a.z * b.x; acc[2][1] += a.z * b.y; acc[2][2] += a.z * b.z; acc[2][3] += a.z * b.w;
            acc[3][0] += a.w * b.x; acc[3][1] += a.w * b.y; acc[3][2] += a.w * b.z; acc[3][3] += a.w * b.w;
        }
        __syncthreads();
    }
    #pragma unroll
    for (int i = 0; i < 4; i++) {
        int row = m0 + tm + i, col = n0 + tn;
        float4 v = make_float4(acc[i][0] + bias[col], acc[i][1] + bias[col + 1],
                               acc[i][2] + bias[col + 2], acc[i][3] + bias[col + 3]);
        if (relu) { v.x = fmaxf(v.x, 0.f); v.y = fmaxf(v.y, 0.f); v.z = fmaxf(v.z, 0.f); v.w = fmaxf(v.w, 0.f); }
        *(float4*)(C + (size_t)row * N + col) = v;
    }
}

__global__ void __launch_bounds__(384) rigid_kernel(const float* __restrict__ rot,
                                                    const float* __restrict__ trans)
{
    __shared__ float sq[144], sk[144];
    int q = blockIdx.x, t = threadIdx.x;
    const float* R = rot + q * 9;
    const float* T = trans + q * 3;
    const float* raw = g_raw + (size_t)q * 1152;
    for (int wi = t; wi < 576; wi += 384) {
        int base, P, lw;
        float* dst;
        if (wi < 144)      { base = 0;   P = 4; lw = wi;       dst = g_qg + q * 144; }
        else if (wi < 288) { base = 144; P = 4; lw = wi - 144; dst = g_kg + q * 144; }
        else               { base = 288; P = 8; lw = wi - 288; dst = g_vg + q * 288; }
        int per = 3 * P;
        int h = lw / per, r = lw - h * per, p = r / 3, i = r - p * 3;
        float l0 = raw[base + h * per + 0 * P + p];
        float l1 = raw[base + h * per + 1 * P + p];
        float l2 = raw[base + h * per + 2 * P + p];
        float v = R[i * 3 + 0] * l0 + R[i * 3 + 1] * l1 + R[i * 3 + 2] * l2 + T[i];
        dst[h * per + p * 3 + i] = v;
        if (wi < 144) sq[lw] = v;
        else if (wi < 288) sk[lw] = v;
    }
    __syncthreads();
    if (t < 24) {
        int h = t % 12;
        const float* sp = (t < 12) ? sq : sk;
        float a = 0.f;
        #pragma unroll
        for (int j = 0; j < 12; j++) { float x = sp[h * 12 + j]; a += x * x; }
        if (t < 12) g_qn[q * 12 + h] = a; else g_kn[q * 12 + h] = a;
    }
    for (int j = t; j < 192; j += 384) g_raw[(size_t)q * 1152 + 576 + j] *= 0.25f;
}

__global__ void __launch_bounds__(128) prep_kernel(const float* __restrict__ tpw)
{
    __shared__ float pw[12];
    int q = blockIdx.x, t = threadIdx.x;
    if (t < 12) pw[t] = 0.23570226039551584f * log1pf(__expf(tpw[t]));
    __syncthreads();
    for (int i = t; i < 336; i += 128) {
        int h = i / 28, j = i - h * 28;
        float u, v;
        if (j < 12) {
            u = g_qg[q * 144 + h * 12 + j] * pw[h] * SC;
            v = g_kg[q * 144 + h * 12 + j];
        } else {
            u = g_raw[(size_t)q * 1152 + 576 + h * 16 + (j - 12)] * SC;
            v = g_raw[(size_t)q * 1152 + 768 + h * 16 + (j - 12)];
        }
        g_u[q * 336 + i] = u;
        g_v[q * 336 + i] = v;
    }
    if (t < 12) {
        g_qadd[q * 12 + t] = -0.5f * SC * pw[t] * g_qn[q * 12 + t];
        g_kadd[q * 12 + t] = -0.5f * SC * pw[t] * g_kn[q * 12 + t];
    }
}

// fused logits: 2 (q,k) pairs x 12 heads per thread
__global__ void __launch_bounds__(256) bias_kernel(
    const float* __restrict__ in2d, const float* __restrict__ w2d,
    const float* __restrict__ b2d, const float* __restrict__ mask)
{
    __shared__ float sw[12][128];
    __shared__ float sb[12];
    int tid = threadIdx.x;
    for (int i = tid; i < 1536; i += 256) {
        int h = i >> 7, c = i & 127;
        sw[h][c] = w2d[c * 12 + h];
    }
    if (tid < 12) sb[tid] = b2d[tid];
    __syncthreads();
    int kx = tid & 15, qy = tid >> 4;
    int q = (blockIdx.y << 4) + qy;
    int kb = (blockIdx.x << 5) + kx;
    const float* p0 = in2d + ((size_t)q * NN + kb) * 128;
    float acc[2][12] = {};
    for (int c = 0; c < 128; c += 8) {
        float4 v00 = *(const float4*)(p0 + c);
        float4 v01 = *(const float4*)(p0 + c + 4);
        float4 v10 = *(const float4*)(p0 + 16 * 128 + c);
        float4 v11 = *(const float4*)(p0 + 16 * 128 + c + 4);
        #pragma unroll
        for (int h = 0; h < 12; h++) {
            float4 w0 = *(const float4*)&sw[h][c];
            float4 w1 = *(const float4*)&sw[h][c + 4];
            acc[0][h] += v00.x * w0.x + v00.y * w0.y + v00.z * w0.z + v00.w * w0.w
                       + v01.x * w1.x + v01.y * w1.y + v01.z * w1.z + v01.w * w1.w;
            acc[1][h] += v10.x * w0.x + v10.y * w0.y + v10.z * w0.z + v10.w * w0.w
                       + v11.x * w1.x + v11.y * w1.y + v11.z * w1.z + v11.w * w1.w;
        }
    }
    float mq = mask[q];
    float mt0 = SC * 1e5f * (1.f - mq * mask[kb]);
    float mt1 = SC * 1e5f * (1.f - mq * mask[kb + 16]);
    const float* up = g_u + q * 336;
    const float* vp0 = g_v + kb * 336;
    const float* vp1 = g_v + (kb + 16) * 336;
    const float* qa = g_qadd + q * 12;
    const float* ka0 = g_kadd + kb * 12;
    const float* ka1 = g_kadd + (kb + 16) * 12;
    #pragma unroll 2
    for (int h = 0; h < 12; h++) {
        float d0 = 0.f, d1 = 0.f;
        #pragma unroll
        for (int jj = 0; jj < 7; jj++) {
            float4 uu = *(const float4*)(up + h * 28 + jj * 4);
            float4 a = *(const float4*)(vp0 + h * 28 + jj * 4);
            float4 b = *(const float4*)(vp1 + h * 28 + jj * 4);
            d0 += uu.x * a.x + uu.y * a.y + uu.z * a.z + uu.w * a.w;
            d1 += uu.x * b.x + uu.y * b.y + uu.z * b.z + uu.w * b.w;
        }
        float base = (acc[0][h] + sb[h]) * SC + qa[h];
        float base1 = (acc[1][h] + sb[h]) * SC + qa[h];
        g_attn[(size_t)h * PLANE + (size_t)q * NN + kb]      = d0 + base  + ka0[h] - mt0;
        g_attn[(size_t)h * PLANE + (size_t)q * NN + kb + 16] = d1 + base1 + ka1[h] - mt1;
    }
}

// warp-shuffle softmax over k (768 per row), 256 threads, 3 short barriers
__global__ void __launch_bounds__(256) softmax_kernel()
{
    __shared__ float sred[8];
    __shared__ float sbc;
    int b = blockIdx.x;
    int h = b / NN, q = b - h * NN;
    float* row = g_attn + (size_t)h * PLANE + (size_t)q * NN;
    int t = threadIdx.x;
    int lane = t & 31, warp = t >> 5;
    float v0 = row[t], v1 = row[t + 256], v2 = row[t + 512];
    float m = fmaxf(v0, fmaxf(v1, v2));
    #pragma unroll
    for (int o = 16; o > 0; o >>= 1) m = fmaxf(m, __shfl_xor_sync(0xffffffff, m, o));
    if (lane == 0) sred[warp] = m;
    __syncthreads();
    if (t == 0) {
        float mm = sred[0];
        #pragma unroll
        for (int i = 1; i < 8; i++) mm = fmaxf(mm, sred[i]);
        sbc = mm;
    }
    __syncthreads();
    m = sbc;
    float e0 = __expf(v0 - m), e1 = __expf(v1 - m), e2 = __expf(v2 - m);
    float s = e0 + e1 + e2;
    #pragma unroll
    for (int o = 16; o > 0; o >>= 1) s += __shfl_xor_sync(0xffffffff, s, o);
    if (lane == 0) sred[warp] = s;
    __syncthreads();
    if (t == 0) {
        float ss = sred[0];
        #pragma unroll
        for (int i = 1; i < 8; i++) ss += sred[i];
        sbc = 1.f / ss;
    }
    __syncthreads();
    float inv = sbc;
    row[t] = e0 * inv; row[t + 256] = e1 * inv; row[t + 512] = e2 * inv;
}

// per-head attn @ [vs|vg]
__global__ void __launch_bounds__(256) headgemm_kernel()
{
    __shared__ float s_attn[64 * 65];
    __shared__ float s_v[64 * 40];
    int tid = threadIdx.x;
    int q0 = blockIdx.x << 6, h = blockIdx.y;
    const float* ap = g_attn + (size_t)h * PLANE;
    int ql = tid & 63, cg = tid >> 6;
    float acc[10] = {};
    for (int kt = 0; kt < NN; kt += 64) {
        #pragma unroll
        for (int i = 0; i < 16; i++) {
            int id = tid + (i << 8);
            int r = id >> 6, c = id & 63;
            s_attn[r * 65 + c] = ap[(size_t)(q0 + r) * NN + kt + c];
        }
        #pragma unroll
        for (int i = 0; i < 10; i++) {
            int id = tid + (i << 8);
            int r = id / 40, c = id - r * 40;
            float v;
            if (c < 16) v = g_raw[(size_t)(kt + r) * 1152 + 960 + h * 16 + c];
            else        v = g_vg[(kt + r) * 288 + h * 24 + (c - 16)];
            s_v[r * 40 + c] = v;
        }
        __syncthreads();
        #pragma unroll 8
        for (int kk = 0; kk < 64; kk++) {
            float a = s_attn[ql * 65 + kk];
            const float* vr = s_v + kk * 40 + cg * 10;
            #pragma unroll
            for (int c = 0; c < 10; c++) acc[c] += a * vr[c];
        }
        __syncthreads();
    }
    int q = q0 + ql;
    #pragma unroll
    for (int c = 0; c < 10; c++) {
        int col = cg * 10 + c;
        if (col < 16) g_final[(size_t)q * 2112 + h * 16 + col] = acc[c];
        else          g_rpg[q * 288 + h * 24 + (col - 16)] = acc[c];
    }
}

// res_2d: split-k halves, attn transposed [k][12h]
__global__ void __launch_bounds__(256) res2d_kernel(const float* __restrict__ in2d)
{
    __shared__ __align__(16) float s_attn[NN * 12];
    __shared__ float s_part[12 * 128];
    int q = blockIdx.x, tid = threadIdx.x;
    #pragma unroll
    for (int h = 0; h < 12; h++)
        for (int k = tid; k < NN; k += 256)
            s_attn[k * 12 + h] = g_attn[(size_t)h * PLANE + (size_t)q * NN + k];
    __syncthreads();
    int c = tid & 127, hg = tid >> 7;
    const float* base = in2d + ((size_t)q * NN + hg * 384) * 128 + c;
    const float* ap = s_attn + hg * 384 * 12;
    float acc[12] = {};
    for (int k0 = 0; k0 < 384; k0 += 8) {
        float vbuf[8];
        #pragma unroll
        for (int j = 0; j < 8; j++)
            vbuf[j] = base[(size_t)(k0 + j) * 128];
        #pragma unroll
        for (int j = 0; j < 8; j++) {
            float v = vbuf[j];
            const float* a = ap + (k0 + j) * 12;
            float4 a0 = *(const float4*)(a);
            float4 a1 = *(const float4*)(a + 4);
            float4 a2 = *(const float4*)(a + 8);
            acc[0] += v * a0.x; acc[1]  += v * a0.y; acc[2]  += v * a0.z; acc[3]  += v * a0.w;
            acc[4] += v * a1.x; acc[5]  += v * a1.y; acc[6]  += v * a1.z; acc[7]  += v * a1.w;
            acc[8] += v * a2.x; acc[9]  += v * a2.y; acc[10] += v * a2.z; acc[11] += v * a2.w;
        }
    }
    if (hg == 1) {
        #pragma unroll
        for (int h = 0; h < 12; h++) s_part[h * 128 + c] = acc[h];
    }
    __syncthreads();
    if (hg == 0) {
        float* f = g_final + (size_t)q * 2112 + 576;
        #pragma unroll
        for (int h = 0; h < 12; h++) f[h * 128 + c] = acc[h] + s_part[h * 128 + c];
    }
}

__global__ void __launch_bounds__(96) rpl_kernel(const float* __restrict__ rot,
                                                 const float* __restrict__ trans)
{
    int q = blockIdx.x, wi = threadIdx.x;
    int h = wi >> 3, p = wi & 7;
    const float* R = rot + q * 9;
    const float* T = trans + q * 3;
    const float* g = g_rpg + q * 288 + h * 24 + p * 3;
    float g0 = g[0] - T[0], g1 = g[1] - T[1], g2 = g[2] - T[2];
    float l0 = R[0] * g0 + R[3] * g1 + R[6] * g2;
    float l1 = R[1] * g0 + R[4] * g1 + R[7] * g2;
    float l2 = R[2] * g0 + R[5] * g1 + R[8] * g2;
    float* f = g_final + (size_t)q * 2112;
    f[192 + h * 8 + p] = l0;
    f[288 + h * 8 + p] = l1;
    f[384 + h * 8 + p] = l2;
    f[480 + h * 8 + p] = sqrtf(fmaxf(l0 * l0 + l1 * l1 + l2 * l2, 1e-16f));
}

__global__ void __launch_bounds__(128) ln_kernel(
    const float* __restrict__ A, const float* __restrict__ B,
    const float* __restrict__ s, const float* __restrict__ bi,
    float* __restrict__ out, int ostride)
{
    __shared__ float r1[128], r2[128];
    int q = blockIdx.x, t = threadIdx.x;
    float x0 = A[q * 384 + t] + B[q * 384 + t];
    float x1 = A[q * 384 + t + 128] + B[q * 384 + t + 128];
    float x2 = A[q * 384 + t + 256] + B[q * 384 + t + 256];
    r1[t] = x0 + x1 + x2;
    r2[t] = x0 * x0 + x1 * x1 + x2 * x2;
    __syncthreads();
    for (int o = 64; o > 0; o >>= 1) {
        if (t < o) { r1[t] += r1[t + o]; r2[t] += r2[t + o]; }
        __syncthreads();
    }
    float mu = r1[0] * (1.f / 384.f);
    float var = r2[0] * (1.f / 384.f) - mu * mu;
    float inv = rsqrtf(var + 1e-5f);
    out[(size_t)q * ostride + t]       = (x0 - mu) * inv * s[t] + bi[t];
    out[(size_t)q * ostride + t + 128] = (x1 - mu) * inv * s[t + 128] + bi[t + 128];
    out[(size_t)q * ostride + t + 256] = (x2 - mu) * inv * s[t + 256] + bi[t + 256];
}

__global__ void __launch_bounds__(192) quat_kernel(
    float* __restrict__ out, const float* __restrict__ rot,
    const float* __restrict__ trans, const float* __restrict__ wq,
    const float* __restrict__ bq)
{
    __shared__ float sv[6];
    int q = blockIdx.x, t = threadIdx.x;
    int warp = t >> 5, lane = t & 31;
    const float* act = out + (size_t)q * 396;
    float acc = 0.f;
    for (int c = lane; c < 384; c += 32) acc += act[c] * wq[c * 6 + warp];
    #pragma unroll
    for (int o = 16; o > 0; o >>= 1) acc += __shfl_down_sync(0xffffffff, acc, o);
    if (lane == 0) sv[warp] = acc + bq[warp];
    __syncthreads();
    if (t == 0) {
        float a = sv[0], b = sv[1], c = sv[2];
        float inv = rsqrtf(1.f + a * a + b * b + c * c);
        float w = inv, x = a * inv, y = b * inv, z = c * inv;
        float ru[9] = {
            1.f - 2.f * (y * y + z * z), 2.f * (x * y - w * z), 2.f * (x * z + w * y),
            2.f * (x * y + w * z), 1.f - 2.f * (x * x + z * z), 2.f * (y * z - w * x),
            2.f * (x * z - w * y), 2.f * (y * z + w * x), 1.f - 2.f * (x * x + y * y)
        };
        const float* R = rot + q * 9;
        const float* T = trans + q * 3;
        float* o9 = out + (size_t)q * 396 + 384;
        #pragma unroll
        for (int i = 0; i < 3; i++)
            #pragma unroll
            for (int j = 0; j < 3; j++)
                o9[i * 3 + j] = R[i * 3 + 0] * ru[0 + j] + R[i * 3 + 1] * ru[3 + j] + R[i * 3 + 2] * ru[6 + j];
        float t0 = sv[3], t1 = sv[4], t2 = sv[5];
        #pragma unroll
        for (int i = 0; i < 3; i++)
            out[(size_t)q * 396 + 393 + i] = R[i * 3 + 0] * t0 + R[i * 3 + 1] * t1 + R[i * 3 + 2] * t2 + T[i];
    }
}

extern "C" void kernel_launch(void* const* d_in, const int* in_sizes, int n_in,
                              void* d_out, int out_size)
{
    const float* in1d  = (const float*)d_in[0];
    const float* in2d  = (const float*)d_in[1];
    const float* mask  = (const float*)d_in[2];
    const float* rot   = (const float*)d_in[3];
    const float* trans = (const float*)d_in[4];
    const float* wqp   = (const float*)d_in[5];
    const float* bqp   = (const float*)d_in[6];
    const float* wkp   = (const float*)d_in[7];
    const float* bkp   = (const float*)d_in[8];
    const float* wvp   = (const float*)d_in[9];
    const float* bvp   = (const float*)d_in[10];
    const float* wqs   = (const float*)d_in[11];
    const float* wks   = (const float*)d_in[12];
    const float* wvs   = (const float*)d_in[13];
    const float* tpw   = (const float*)d_in[14];
    const float* w2d   = (const float*)d_in[15];
    const float* b2d   = (const float*)d_in[16];
    const float* wout  = (const float*)d_in[17];
    const float* bout  = (const float*)d_in[18];
    const float* ln1s  = (const float*)d_in[19];
    const float* ln1b  = (const float*)d_in[20];
    const float* wt1   = (const float*)d_in[21];
    const float* bt1   = (const float*)d_in[22];
    const float* wt2   = (const float*)d_in[23];
    const float* bt2   = (const float*)d_in[24];
    const float* wt3   = (const float*)d_in[25];
    const float* bt3   = (const float*)d_in[26];
    const float* ln2s  = (const float*)d_in[27];
    const float* ln2b  = (const float*)d_in[28];
    const float* wquat = (const float*)d_in[29];
    const float* bquat = (const float*)d_in[30];
    float* out = (float*)d_out;

    float *p_wcat, *p_bcat, *p_raw, *p_final, *p_tmp, *p_act1, *p_x1, *p_x2;
    cudaGetSymbolAddress((void**)&p_wcat, g_wcat);
    cudaGetSymbolAddress((void**)&p_bcat, g_bcat);
    cudaGetSymbolAddress((void**)&p_raw, g_raw);
    cudaGetSymbolAddress((void**)&p_final, g_final);
    cudaGetSymbolAddress((void**)&p_tmp, g_tmp);
    cudaGetSymbolAddress((void**)&p_act1, g_act1);
    cudaGetSymbolAddress((void**)&p_x1, g_x1);
    cudaGetSymbolAddress((void**)&p_x2, g_x2);

    pack_kernel<<<(CC * 1152 + 255) / 256, 256>>>(wqp, wkp, wvp, wqs, wks, wvs, bqp, bkp, bvp);
    gemm_kernel<<<dim3(1152 / 64, NN / 32), 128>>>(in1d, p_wcat, p_bcat, p_raw, NN, 1152, CC, 0);
    rigid_kernel<<<NN, 384>>>(rot, trans);
    prep_kernel<<<NN, 128>>>(tpw);
    bias_kernel<<<dim3(NN / 32, NN / 16), 256>>>(in2d, w2d, b2d, mask);
    softmax_kernel<<<HH * NN, 256>>>();
    headgemm_kernel<<<dim3(NN / 64, HH), 256>>>();
    res2d_kernel<<<NN, 256>>>(in2d);
    rpl_kernel<<<NN, 96>>>(rot, trans);
    gemm_kernel<<<dim3(CC / 64, NN / 32), 128>>>(p_final, wout, bout, p_tmp, NN, CC, 2112, 0);
    ln_kernel<<<NN, 128>>>(in1d, p_tmp, ln1s, ln1b, p_act1, 384);
    gemm_kernel<<<dim3(CC / 64, NN / 32), 128>>>(p_act1, wt1, bt1, p_x1, NN, CC, CC, 1);
    gemm_kernel<<<dim3(CC / 64, NN / 32), 128>>>(p_x1, wt2, bt2, p_x2, NN, CC, CC, 1);
    gemm_kernel<<<dim3(CC / 64, NN / 32), 128>>>(p_x2, wt3, bt3, p_tmp, NN, CC, CC, 0);
    ln_kernel<<<NN, 128>>>(p_act1, p_tmp, ln2s, ln2b, out, 396);
    quat_kernel<<<NN, 192>>>(out, rot, trans, wquat, bquat);
}

// round 16
// speedup vs baseline: 1.5323x; 1.0633x over previous
#include <cuda_runtime.h>
#include <math.h>

#define NN 768
#define CC 384
#define HH 12
#define PLANE (NN * NN)
#define SC 0.57735026919f

__device__ float g_wcat[CC * 1152];
__device__ float g_bcat[1152];
__device__ float g_raw[NN * 1152];   // [q][qpt144|kpt144|vpt288|qs192|ks192|vs192]
__device__ float g_qg[NN * 144];
__device__ float g_kg[NN * 144];
__device__ float g_vg[NN * 288];
__device__ float g_qn[NN * HH];
__device__ float g_kn[NN * HH];
__device__ float g_u[NN * 336];
__device__ float g_v[NN * 336];
__device__ float g_qadd[NN * HH];
__device__ float g_kadd[NN * HH];
__device__ float g_attn[(size_t)HH * PLANE];
__device__ float g_rpg[NN * 288];
__device__ float g_final[NN * 2112];
__device__ float g_tmp[NN * CC];
__device__ float g_act1[NN * CC];
__device__ float g_x1[NN * CC];
__device__ float g_x2[NN * CC];

__global__ void pack_kernel(const float* __restrict__ wq, const float* __restrict__ wk,
                            const float* __restrict__ wv, const float* __restrict__ wqs,
                            const float* __restrict__ wks, const float* __restrict__ wvs,
                            const float* __restrict__ bq, const float* __restrict__ bk,
                            const float* __restrict__ bv)
{
    int idx = blockIdx.x * blockDim.x + threadIdx.x;
    if (idx < CC * 1152) {
        int c = idx / 1152, o = idx - c * 1152;
        float v;
        if (o < 144)      v = wq[c * 144 + o];
        else if (o < 288) v = wk[c * 144 + (o - 144)];
        else if (o < 576) v = wv[c * 288 + (o - 288)];
        else if (o < 768) v = wqs[c * 192 + (o - 576)];
        else if (o < 960) v = wks[c * 192 + (o - 768)];
        else              v = wvs[c * 192 + (o - 960)];
        g_wcat[idx] = v;
    }
    if (idx < 1152) {
        float b = 0.f;
        if (idx < 144)      b = bq[idx];
        else if (idx < 288) b = bk[idx - 144];
        else if (idx < 576) b = bv[idx - 288];
        g_bcat[idx] = b;
    }
}

// C[M,N]=A[M,K]@W[K,N]+bias (M%64==0,N%32==0,K%32==0)  (R2/R13 proven version)
__global__ void __launch_bounds__(256) gemm_kernel(
    const float* __restrict__ A, const float* __restrict__ W,
    const float* __restrict__ bias, float* __restrict__ C,
    int M, int N, int K, int relu)
{
    __shared__ float sA[64][36];
    __shared__ float sB[32][32];
    int tid = threadIdx.x;
    int tx = tid & 7, ty = tid >> 3;
    int m0 = blockIdx.y << 6, n0 = blockIdx.x << 5;
    float acc[2][4] = {};
    for (int k0 = 0; k0 < K; k0 += 32) {
        #pragma unroll
        for (int i = 0; i < 2; i++) {
            int id = tid + (i << 8);
            int r = id >> 3, kq = id & 7;
            float4 v = *(const float4*)(A + (size_t)(m0 + r) * K + k0 + (kq << 2));
            *(float4*)&sA[r][kq << 2] = v;
        }
        {
            int r = tid >> 3, cq = tid & 7;
            float4 v = *(const float4*)(W + (size_t)(k0 + r) * N + n0 + (cq << 2));
            *(float4*)&sB[r][cq << 2] = v;
        }
        __syncthreads();
        #pragma unroll
        for (int kk = 0; kk < 32; kk++) {
            float a0 = sA[(ty << 1) + 0][kk];
            float a1 = sA[(ty << 1) + 1][kk];
            float4 b = *(const float4*)&sB[kk][tx << 2];
            acc[0][0] += a0 * b.x; acc[0][1] += a0 * b.y; acc[0][2] += a0 * b.z; acc[0][3] += a0 * b.w;
            acc[1][0] += a1 * b.x; acc[1][1] += a1 * b.y; acc[1][2] += a1 * b.z; acc[1][3] += a1 * b.w;
        }
        __syncthreads();
    }
    #pragma unroll
    for (int i = 0; i < 2; i++)
        #pragma unroll
        for (int j = 0; j < 4; j++) {
            int row = m0 + (ty << 1) + i, col = n0 + (tx << 2) + j;
            float v = acc[i][j] + bias[col];
            if (relu) v = fmaxf(v, 0.f);
            C[(size_t)row * N + col] = v;
        }
}

__global__ void __launch_bounds__(384) rigid_kernel(const float* __restrict__ rot,
                                                    const float* __restrict__ trans)
{
    __shared__ float sq[144], sk[144];
    int q = blockIdx.x, t = threadIdx.x;
    const float* R = rot + q * 9;
    const float* T = trans + q * 3;
    const float* raw = g_raw + (size_t)q * 1152;
    for (int wi = t; wi < 576; wi += 384) {
        int base, P, lw;
        float* dst;
        if (wi < 144)      { base = 0;   P = 4; lw = wi;       dst = g_qg + q * 144; }
        else if (wi < 288) { base = 144; P = 4; lw = wi - 144; dst = g_kg + q * 144; }
        else               { base = 288; P = 8; lw = wi - 288; dst = g_vg + q * 288; }
        int per = 3 * P;
        int h = lw / per, r = lw - h * per, p = r / 3, i = r - p * 3;
        float l0 = raw[base + h * per + 0 * P + p];
        float l1 = raw[base + h * per + 1 * P + p];
        float l2 = raw[base + h * per + 2 * P + p];
        float v = R[i * 3 + 0] * l0 + R[i * 3 + 1] * l1 + R[i * 3 + 2] * l2 + T[i];
        dst[h * per + p * 3 + i] = v;
        if (wi < 144) sq[lw] = v;
        else if (wi < 288) sk[lw] = v;
    }
    __syncthreads();
    if (t < 24) {
        int h = t % 12;
        const float* sp = (t < 12) ? sq : sk;
        float a = 0.f;
        #pragma unroll
        for (int j = 0; j < 12; j++) { float x = sp[h * 12 + j]; a += x * x; }
        if (t < 12) g_qn[q * 12 + h] = a; else g_kn[q * 12 + h] = a;
    }
    for (int j = t; j < 192; j += 384) g_raw[(size_t)q * 1152 + 576 + j] *= 0.25f;
}

__global__ void __launch_bounds__(128) prep_kernel(const float* __restrict__ tpw)
{
    __shared__ float pw[12];
    int q = blockIdx.x, t = threadIdx.x;
    if (t < 12) pw[t] = 0.23570226039551584f * log1pf(__expf(tpw[t]));
    __syncthreads();
    for (int i = t; i < 336; i += 128) {
        int h = i / 28, j = i - h * 28;
        float u, v;
        if (j < 12) {
            u = g_qg[q * 144 + h * 12 + j] * pw[h] * SC;
            v = g_kg[q * 144 + h * 12 + j];
        } else {
            u = g_raw[(size_t)q * 1152 + 576 + h * 16 + (j - 12)] * SC;
            v = g_raw[(size_t)q * 1152 + 768 + h * 16 + (j - 12)];
        }
        g_u[q * 336 + i] = u;
        g_v[q * 336 + i] = v;
    }
    if (t < 12) {
        g_qadd[q * 12 + t] = -0.5f * SC * pw[t] * g_qn[q * 12 + t];
        g_kadd[q * 12 + t] = -0.5f * SC * pw[t] * g_kn[q * 12 + t];
    }
}

// fused logits: 2 (q,k) pairs x 12 heads per thread
__global__ void __launch_bounds__(256) bias_kernel(
    const float* __restrict__ in2d, const float* __restrict__ w2d,
    const float* __restrict__ b2d, const float* __restrict__ mask)
{
    __shared__ float sw[12][128];
    __shared__ float sb[12];
    int tid = threadIdx.x;
    for (int i = tid; i < 1536; i += 256) {
        int h = i >> 7, c = i & 127;
        sw[h][c] = w2d[c * 12 + h];
    }
    if (tid < 12) sb[tid] = b2d[tid];
    __syncthreads();
    int kx = tid & 15, qy = tid >> 4;
    int q = (blockIdx.y << 4) + qy;
    int kb = (blockIdx.x << 5) + kx;
    const float* p0 = in2d + ((size_t)q * NN + kb) * 128;
    float acc[2][12] = {};
    for (int c = 0; c < 128; c += 8) {
        float4 v00 = *(const float4*)(p0 + c);
        float4 v01 = *(const float4*)(p0 + c + 4);
        float4 v10 = *(const float4*)(p0 + 16 * 128 + c);
        float4 v11 = *(const float4*)(p0 + 16 * 128 + c + 4);
        #pragma unroll
        for (int h = 0; h < 12; h++) {
            float4 w0 = *(const float4*)&sw[h][c];
            float4 w1 = *(const float4*)&sw[h][c + 4];
            acc[0][h] += v00.x * w0.x + v00.y * w0.y + v00.z * w0.z + v00.w * w0.w
                       + v01.x * w1.x + v01.y * w1.y + v01.z * w1.z + v01.w * w1.w;
            acc[1][h] += v10.x * w0.x + v10.y * w0.y + v10.z * w0.z + v10.w * w0.w
                       + v11.x * w1.x + v11.y * w1.y + v11.z * w1.z + v11.w * w1.w;
        }
    }
    float mq = mask[q];
    float mt0 = SC * 1e5f * (1.f - mq * mask[kb]);
    float mt1 = SC * 1e5f * (1.f - mq * mask[kb + 16]);
    const float* up = g_u + q * 336;
    const float* vp0 = g_v + kb * 336;
    const float* vp1 = g_v + (kb + 16) * 336;
    const float* qa = g_qadd + q * 12;
    const float* ka0 = g_kadd + kb * 12;
    const float* ka1 = g_kadd + (kb + 16) * 12;
    #pragma unroll 2
    for (int h = 0; h < 12; h++) {
        float d0 = 0.f, d1 = 0.f;
        #pragma unroll
        for (int jj = 0; jj < 7; jj++) {
            float4 uu = *(const float4*)(up + h * 28 + jj * 4);
            float4 a = *(const float4*)(vp0 + h * 28 + jj * 4);
            float4 b = *(const float4*)(vp1 + h * 28 + jj * 4);
            d0 += uu.x * a.x + uu.y * a.y + uu.z * a.z + uu.w * a.w;
            d1 += uu.x * b.x + uu.y * b.y + uu.z * b.z + uu.w * b.w;
        }
        float base = (acc[0][h] + sb[h]) * SC + qa[h];
        float base1 = (acc[1][h] + sb[h]) * SC + qa[h];
        g_attn[(size_t)h * PLANE + (size_t)q * NN + kb]      = d0 + base  + ka0[h] - mt0;
        g_attn[(size_t)h * PLANE + (size_t)q * NN + kb + 16] = d1 + base1 + ka1[h] - mt1;
    }
}

// warp-shuffle softmax over k (768 per row), 256 threads, 3 short barriers
__global__ void __launch_bounds__(256) softmax_kernel()
{
    __shared__ float sred[8];
    __shared__ float sbc;
    int b = blockIdx.x;
    int h = b / NN, q = b - h * NN;
    float* row = g_attn + (size_t)h * PLANE + (size_t)q * NN;
    int t = threadIdx.x;
    int lane = t & 31, warp = t >> 5;
    float v0 = row[t], v1 = row[t + 256], v2 = row[t + 512];
    float m = fmaxf(v0, fmaxf(v1, v2));
    #pragma unroll
    for (int o = 16; o > 0; o >>= 1) m = fmaxf(m, __shfl_xor_sync(0xffffffff, m, o));
    if (lane == 0) sred[warp] = m;
    __syncthreads();
    if (t == 0) {
        float mm = sred[0];
        #pragma unroll
        for (int i = 1; i < 8; i++) mm = fmaxf(mm, sred[i]);
        sbc = mm;
    }
    __syncthreads();
    m = sbc;
    float e0 = __expf(v0 - m), e1 = __expf(v1 - m), e2 = __expf(v2 - m);
    float s = e0 + e1 + e2;
    #pragma unroll
    for (int o = 16; o > 0; o >>= 1) s += __shfl_xor_sync(0xffffffff, s, o);
    if (lane == 0) sred[warp] = s;
    __syncthreads();
    if (t == 0) {
        float ss = sred[0];
        #pragma unroll
        for (int i = 1; i < 8; i++) ss += sred[i];
        sbc = 1.f / ss;
    }
    __syncthreads();
    float inv = sbc;
    row[t] = e0 * inv; row[t + 256] = e1 * inv; row[t + 512] = e2 * inv;
}

// merged consumers: y==0 -> res2d (q=x); y==1, x<144 -> headgemm (h=x/12, q0=(x%12)*64)
__global__ void __launch_bounds__(256) consumers_kernel(const float* __restrict__ in2d)
{
    __shared__ __align__(16) float sm[NN * 12 + 12 * 128];   // 42KB pool
    int tid = threadIdx.x;
    if (blockIdx.y == 0) {
        // ---- res2d: split-k halves, attn transposed [k][12h] ----
        float* s_attn = sm;                 // NN*12
        float* s_part = sm + NN * 12;       // 12*128
        int q = blockIdx.x;
        #pragma unroll
        for (int h = 0; h < 12; h++)
            for (int k = tid; k < NN; k += 256)
                s_attn[k * 12 + h] = g_attn[(size_t)h * PLANE + (size_t)q * NN + k];
        __syncthreads();
        int c = tid & 127, hg = tid >> 7;
        const float* base = in2d + ((size_t)q * NN + hg * 384) * 128 + c;
        const float* ap = s_attn + hg * 384 * 12;
        float acc[12] = {};
        for (int k0 = 0; k0 < 384; k0 += 8) {
            float vbuf[8];
            #pragma unroll
            for (int j = 0; j < 8; j++)
                vbuf[j] = base[(size_t)(k0 + j) * 128];
            #pragma unroll
            for (int j = 0; j < 8; j++) {
                float v = vbuf[j];
                const float* a = ap + (k0 + j) * 12;
                float4 a0 = *(const float4*)(a);
                float4 a1 = *(const float4*)(a + 4);
                float4 a2 = *(const float4*)(a + 8);
                acc[0] += v * a0.x; acc[1]  += v * a0.y; acc[2]  += v * a0.z; acc[3]  += v * a0.w;
                acc[4] += v * a1.x; acc[5]  += v * a1.y; acc[6]  += v * a1.z; acc[7]  += v * a1.w;
                acc[8] += v * a2.x; acc[9]  += v * a2.y; acc[10] += v * a2.z; acc[11] += v * a2.w;
            }
        }
        if (hg == 1) {
            #pragma unroll
            for (int h = 0; h < 12; h++) s_part[h * 128 + c] = acc[h];
        }
        __syncthreads();
        if (hg == 0) {
            float* f = g_final + (size_t)q * 2112 + 576;
            #pragma unroll
            for (int h = 0; h < 12; h++) f[h * 128 + c] = acc[h] + s_part[h * 128 + c];
        }
    } else {
        if (blockIdx.x >= 144) return;
        // ---- headgemm: per-head attn @ [vs|vg] ----
        float* s_attn = sm;                 // 64*65 = 4160
        float* s_v = sm + 64 * 65;          // 64*40 = 2560
        int h = blockIdx.x / 12;
        int q0 = (blockIdx.x - h * 12) << 6;
        const float* ap = g_attn + (size_t)h * PLANE;
        int ql = tid & 63, cg = tid >> 6;
        float acc[10] = {};
        for (int kt = 0; kt < NN; kt += 64) {
            #pragma unroll
            for (int i = 0; i < 16; i++) {
                int id = tid + (i << 8);
                int r = id >> 6, c = id & 63;
                s_attn[r * 65 + c] = ap[(size_t)(q0 + r) * NN + kt + c];
            }
            #pragma unroll
            for (int i = 0; i < 10; i++) {
                int id = tid + (i << 8);
                int r = id / 40, c = id - r * 40;
                float v;
                if (c < 16) v = g_raw[(size_t)(kt + r) * 1152 + 960 + h * 16 + c];
                else        v = g_vg[(kt + r) * 288 + h * 24 + (c - 16)];
                s_v[r * 40 + c] = v;
            }
            __syncthreads();
            #pragma unroll 8
            for (int kk = 0; kk < 64; kk++) {
                float a = s_attn[ql * 65 + kk];
                const float* vr = s_v + kk * 40 + cg * 10;
                #pragma unroll
                for (int c = 0; c < 10; c++) acc[c] += a * vr[c];
            }
            __syncthreads();
        }
        int q = q0 + ql;
        #pragma unroll
        for (int c = 0; c < 10; c++) {
            int col = cg * 10 + c;
            if (col < 16) g_final[(size_t)q * 2112 + h * 16 + col] = acc[c];
            else          g_rpg[q * 288 + h * 24 + (col - 16)] = acc[c];
        }
    }
}

__global__ void __launch_bounds__(96) rpl_kernel(const float* __restrict__ rot,
                                                 const float* __restrict__ trans)
{
    int q = blockIdx.x, wi = threadIdx.x;
    int h = wi >> 3, p = wi & 7;
    const float* R = rot + q * 9;
    const float* T = trans + q * 3;
    const float* g = g_rpg + q * 288 + h * 24 + p * 3;
    float g0 = g[0] - T[0], g1 = g[1] - T[1], g2 = g[2] - T[2];
    float l0 = R[0] * g0 + R[3] * g1 + R[6] * g2;
    float l1 = R[1] * g0 + R[4] * g1 + R[7] * g2;
    float l2 = R[2] * g0 + R[5] * g1 + R[8] * g2;
    float* f = g_final + (size_t)q * 2112;
    f[192 + h * 8 + p] = l0;
    f[288 + h * 8 + p] = l1;
    f[384 + h * 8 + p] = l2;
    f[480 + h * 8 + p] = sqrtf(fmaxf(l0 * l0 + l1 * l1 + l2 * l2, 1e-16f));
}

__global__ void __launch_bounds__(128) ln_kernel(
    const float* __restrict__ A, const float* __restrict__ B,
    const float* __restrict__ s, const float* __restrict__ bi,
    float* __restrict__ out, int ostride)
{
    __shared__ float r1[128], r2[128];
    int q = blockIdx.x, t = threadIdx.x;
    float x0 = A[q * 384 + t] + B[q * 384 + t];
    float x1 = A[q * 384 + t + 128] + B[q * 384 + t + 128];
    float x2 = A[q * 384 + t + 256] + B[q * 384 + t + 256];
    r1[t] = x0 + x1 + x2;
    r2[t] = x0 * x0 + x1 * x1 + x2 * x2;
    __syncthreads();
    for (int o = 64; o > 0; o >>= 1) {
        if (t < o) { r1[t] += r1[t + o]; r2[t] += r2[t + o]; }
        __syncthreads();
    }
    float mu = r1[0] * (1.f / 384.f);
    float var = r2[0] * (1.f / 384.f) - mu * mu;
    float inv = rsqrtf(var + 1e-5f);
    out[(size_t)q * ostride + t]       = (x0 - mu) * inv * s[t] + bi[t];
    out[(size_t)q * ostride + t + 128] = (x1 - mu) * inv * s[t + 128] + bi[t + 128];
    out[(size_t)q * ostride + t + 256] = (x2 - mu) * inv * s[t + 256] + bi[t + 256];
}

__global__ void __launch_bounds__(192) quat_kernel(
    float* __restrict__ out, const float* __restrict__ rot,
    const float* __restrict__ trans, const float* __restrict__ wq,
    const float* __restrict__ bq)
{
    __shared__ float sv[6];
    int q = blockIdx.x, t = threadIdx.x;
    int warp = t >> 5, lane = t & 31;
    const float* act = out + (size_t)q * 396;
    float acc = 0.f;
    for (int c = lane; c < 384; c += 32) acc += act[c] * wq[c * 6 + warp];
    #pragma unroll
    for (int o = 16; o > 0; o >>= 1) acc += __shfl_down_sync(0xffffffff, acc, o);
    if (lane == 0) sv[warp] = acc + bq[warp];
    __syncthreads();
    if (t == 0) {
        float a = sv[0], b = sv[1], c = sv[2];
        float inv = rsqrtf(1.f + a * a + b * b + c * c);
        float w = inv, x = a * inv, y = b * inv, z = c * inv;
        float ru[9] = {
            1.f - 2.f * (y * y + z * z), 2.f * (x * y - w * z), 2.f * (x * z + w * y),
            2.f * (x * y + w * z), 1.f - 2.f * (x * x + z * z), 2.f * (y * z - w * x),
            2.f * (x * z - w * y), 2.f * (y * z + w * x), 1.f - 2.f * (x * x + y * y)
        };
        const float* R = rot + q * 9;
        const float* T = trans + q * 3;
        float* o9 = out + (size_t)q * 396 + 384;
        #pragma unroll
        for (int i = 0; i < 3; i++)
            #pragma unroll
            for (int j = 0; j < 3; j++)
                o9[i * 3 + j] = R[i * 3 + 0] * ru[0 + j] + R[i * 3 + 1] * ru[3 + j] + R[i * 3 + 2] * ru[6 + j];
        float t0 = sv[3], t1 = sv[4], t2 = sv[5];
        #pragma unroll
        for (int i = 0; i < 3; i++)
            out[(size_t)q * 396 + 393 + i] = R[i * 3 + 0] * t0 + R[i * 3 + 1] * t1 + R[i * 3 + 2] * t2 + T[i];
    }
}

extern "C" void kernel_launch(void* const* d_in, const int* in_sizes, int n_in,
                              void* d_out, int out_size)
{
    const float* in1d  = (const float*)d_in[0];
    const float* in2d  = (const float*)d_in[1];
    const float* mask  = (const float*)d_in[2];
    const float* rot   = (const float*)d_in[3];
    const float* trans = (const float*)d_in[4];
    const float* wqp   = (const float*)d_in[5];
    const float* bqp   = (const float*)d_in[6];
    const float* wkp   = (const float*)d_in[7];
    const float* bkp   = (const float*)d_in[8];
    const float* wvp   = (const float*)d_in[9];
    const float* bvp   = (const float*)d_in[10];
    const float* wqs   = (const float*)d_in[11];
    const float* wks   = (const float*)d_in[12];
    const float* wvs   = (const float*)d_in[13];
    const float* tpw   = (const float*)d_in[14];
    const float* w2d   = (const float*)d_in[15];
    const float* b2d   = (const float*)d_in[16];
    const float* wout  = (const float*)d_in[17];
    const float* bout  = (const float*)d_in[18];
    const float* ln1s  = (const float*)d_in[19];
    const float* ln1b  = (const float*)d_in[20];
    const float* wt1   = (const float*)d_in[21];
    const float* bt1   = (const float*)d_in[22];
    const float* wt2   = (const float*)d_in[23];
    const float* bt2   = (const float*)d_in[24];
    const float* wt3   = (const float*)d_in[25];
    const float* bt3   = (const float*)d_in[26];
    const float* ln2s  = (const float*)d_in[27];
    const float* ln2b  = (const float*)d_in[28];
    const float* wquat = (const float*)d_in[29];
    const float* bquat = (const float*)d_in[30];
    float* out = (float*)d_out;

    float *p_wcat, *p_bcat, *p_raw, *p_final, *p_tmp, *p_act1, *p_x1, *p_x2;
    cudaGetSymbolAddress((void**)&p_wcat, g_wcat);
    cudaGetSymbolAddress((void**)&p_bcat, g_bcat);
    cudaGetSymbolAddress((void**)&p_raw, g_raw);
    cudaGetSymbolAddress((void**)&p_final, g_final);
    cudaGetSymbolAddress((void**)&p_tmp, g_tmp);
    cudaGetSymbolAddress((void**)&p_act1, g_act1);
    cudaGetSymbolAddress((void**)&p_x1, g_x1);
    cudaGetSymbolAddress((void**)&p_x2, g_x2);

    pack_kernel<<<(CC * 1152 + 255) / 256, 256>>>(wqp, wkp, wvp, wqs, wks, wvs, bqp, bkp, bvp);
    gemm_kernel<<<dim3(1152 / 32, NN / 64), 256>>>(in1d, p_wcat, p_bcat, p_raw, NN, 1152, CC, 0);
    rigid_kernel<<<NN, 384>>>(rot, trans);
    prep_kernel<<<NN, 128>>>(tpw);
    bias_kernel<<<dim3(NN / 32, NN / 16), 256>>>(in2d, w2d, b2d, mask);
    softmax_kernel<<<HH * NN, 256>>>();
    consumers_kernel<<<dim3(NN, 2), 256>>>(in2d);
    rpl_kernel<<<NN, 96>>>(rot, trans);
    gemm_kernel<<<dim3(CC / 32, NN / 64), 256>>>(p_final, wout, bout, p_tmp, NN, CC, 2112, 0);
    ln_kernel<<<NN, 128>>>(in1d, p_tmp, ln1s, ln1b, p_act1, 384);
    gemm_kernel<<<dim3(CC / 32, NN / 64), 256>>>(p_act1, wt1, bt1, p_x1, NN, CC, CC, 1);
    gemm_kernel<<<dim3(CC / 32, NN / 64), 256>>>(p_x1, wt2, bt2, p_x2, NN, CC, CC, 1);
    gemm_kernel<<<dim3(CC / 32, NN / 64), 256>>>(p_x2, wt3, bt3, p_tmp, NN, CC, CC, 0);
    ln_kernel<<<NN, 128>>>(p_act1, p_tmp, ln2s, ln2b, out, 396);
    quat_kernel<<<NN, 192>>>(out, rot, trans, wquat, bquat);
}